// round 1
// baseline (speedup 1.0000x reference)
#include <cuda_runtime.h>
#include <cstdint>
#include <cstddef>

// ---------------------------------------------------------------------------
// DataDependentRBFKernel
//   sigma = MLP(embeddings)  (256 -> 32 -> 16 -> 1, exact gelu, sigmoid,
//                             affine to [0.1, 10])
//   out[b,n,m] = exp(-||z[m] - mu[b,n]||^2 / (2 sigma[b,n]^2))
//
// Kernel 1 (sigma_kernel): per-row MLP, writes sc = -log2(e)/(2 sigma^2)
//                          into __device__ scratch g_scale.
// Kernel 2 (rbf_kernel):   store-bandwidth-bound sweep producing 64 MiB out.
// ---------------------------------------------------------------------------

#define EDIM 256
#define H1DIM 32
#define H2DIM 16

__device__ float g_scale[65536];  // scratch: B*N = 8192 rows (margin to 64k)

__device__ __forceinline__ float ex2_approx(float x) {
    float y;
    asm("ex2.approx.f32 %0, %1;" : "=f"(y) : "f"(x));
    return y;
}

__device__ __forceinline__ float gelu_exact(float x) {
    return 0.5f * x * (1.0f + erff(x * 0.70710678118654752440f));
}

// -------------------- sigma MLP: 8 rows per 256-thread block ---------------
__global__ __launch_bounds__(256)
void sigma_kernel(const float* __restrict__ emb,
                  const float* __restrict__ w1, const float* __restrict__ b1,
                  const float* __restrict__ w2, const float* __restrict__ b2,
                  const float* __restrict__ w3, const float* __restrict__ b3,
                  int BN)
{
    __shared__ float e_s[8 * EDIM];          // 8 KB
    __shared__ float w1_s[EDIM * H1DIM];     // 32 KB, [k][j] (j contiguous)
    __shared__ float h1_s[8 * H1DIM];
    __shared__ float h2_s[8 * H2DIM];

    const int tid = threadIdx.x;
    const int rowbase = blockIdx.x * 8;

    // cooperative loads (float4, coalesced)
    {
        const float4* e4 = reinterpret_cast<const float4*>(emb + (size_t)rowbase * EDIM);
        float4* es4 = reinterpret_cast<float4*>(e_s);
        #pragma unroll
        for (int i = 0; i < (8 * EDIM / 4) / 256; ++i)       // 2 iters
            es4[tid + i * 256] = e4[tid + i * 256];

        const float4* w14 = reinterpret_cast<const float4*>(w1);
        float4* w1s4 = reinterpret_cast<float4*>(w1_s);
        #pragma unroll
        for (int i = 0; i < (EDIM * H1DIM / 4) / 256; ++i)   // 8 iters
            w1s4[tid + i * 256] = w14[tid + i * 256];
    }
    __syncthreads();

    // layer 1: warp per row, lane = output unit j
    {
        const int j = tid & 31;
        const int r = tid >> 5;
        float acc = __ldg(&b1[j]);
        #pragma unroll 4
        for (int k = 0; k < EDIM; k += 4) {
            float4 ev = *reinterpret_cast<const float4*>(&e_s[r * EDIM + k]);
            acc = fmaf(ev.x, w1_s[(k + 0) * H1DIM + j], acc);
            acc = fmaf(ev.y, w1_s[(k + 1) * H1DIM + j], acc);
            acc = fmaf(ev.z, w1_s[(k + 2) * H1DIM + j], acc);
            acc = fmaf(ev.w, w1_s[(k + 3) * H1DIM + j], acc);
        }
        h1_s[r * H1DIM + j] = gelu_exact(acc);
    }
    __syncthreads();

    // layer 2: 8 rows x 16 units = 128 threads
    if (tid < 8 * H2DIM) {
        const int r = tid >> 4;
        const int m = tid & 15;
        float acc = __ldg(&b2[m]);
        #pragma unroll
        for (int j = 0; j < H1DIM; ++j)
            acc = fmaf(h1_s[r * H1DIM + j], __ldg(&w2[j * H2DIM + m]), acc);
        h2_s[r * H2DIM + m] = gelu_exact(acc);
    }
    __syncthreads();

    // layer 3 + sigmoid + affine + fold log2(e) into the scale
    if (tid < 8) {
        float s = __ldg(&b3[0]);
        #pragma unroll
        for (int m = 0; m < H2DIM; ++m)
            s = fmaf(h2_s[tid * H2DIM + m], __ldg(&w3[m]), s);
        float sig = 1.0f / (1.0f + expf(-s));
        float sigma = 0.1f + 9.9f * sig;
        // arg2 (base-2 exponent) = sc * d2 with sc = -log2(e) / (2 sigma^2)
        g_scale[rowbase + tid] = -1.44269504088896340736f / (2.0f * sigma * sigma);
    }
}

// -------------------- RBF sweep: 16 rows per 256-thread block --------------
// Thread t owns z points m = t*8 .. t*8+7 (held in registers across all rows).
__global__ __launch_bounds__(256)
void rbf_kernel(const float* __restrict__ z, const float* __restrict__ mu,
                float* __restrict__ out, int M)
{
    constexpr int TILE_R = 16;
    __shared__ float  sc_s[TILE_R];
    __shared__ float2 mu_s[TILE_R];

    const int t = threadIdx.x;
    const int rowbase = blockIdx.x * TILE_R;

    if (t < TILE_R) {
        sc_s[t] = g_scale[rowbase + t];
        mu_s[t] = reinterpret_cast<const float2*>(mu)[rowbase + t];
    }

    // load 8 z points into registers: z is [M,2] interleaved -> 4x float4
    float z0[8], z1[8], r2[8];
    {
        const float4* z4 = reinterpret_cast<const float4*>(z);
        #pragma unroll
        for (int i = 0; i < 4; ++i) {
            float4 v = z4[t * 4 + i];
            z0[2 * i]     = v.x;  z1[2 * i]     = v.y;
            z0[2 * i + 1] = v.z;  z1[2 * i + 1] = v.w;
        }
        #pragma unroll
        for (int i = 0; i < 8; ++i)
            r2[i] = z0[i] * z0[i] + z1[i] * z1[i];
    }
    __syncthreads();

    const size_t base = (size_t)rowbase * (size_t)M + (size_t)t * 8;

    #pragma unroll 4
    for (int r = 0; r < TILE_R; ++r) {
        const float  sc = sc_s[r];
        const float2 muv = mu_s[r];
        const float  c0 = -2.0f * sc * muv.x;
        const float  c1 = -2.0f * sc * muv.y;
        const float  cc = sc * (muv.x * muv.x + muv.y * muv.y);

        float o[8];
        #pragma unroll
        for (int i = 0; i < 8; ++i) {
            float a = fmaf(sc, r2[i], fmaf(c0, z0[i], fmaf(c1, z1[i], cc)));
            o[i] = ex2_approx(a);
        }
        float4* o4 = reinterpret_cast<float4*>(out + base + (size_t)r * M);
        o4[0] = make_float4(o[0], o[1], o[2], o[3]);
        o4[1] = make_float4(o[4], o[5], o[6], o[7]);
    }
}

// ---------------------------------------------------------------------------
extern "C" void kernel_launch(void* const* d_in, const int* in_sizes, int n_in,
                              void* d_out, int out_size)
{
    const float* z   = (const float*)d_in[0];   // [M, 2]
    const float* mu  = (const float*)d_in[1];   // [B, N, 2]
    const float* emb = (const float*)d_in[2];   // [B, N, 256]
    const float* w1  = (const float*)d_in[3];   // [256, 32]
    const float* b1  = (const float*)d_in[4];   // [32]
    const float* w2  = (const float*)d_in[5];   // [32, 16]
    const float* b2  = (const float*)d_in[6];   // [16]
    const float* w3  = (const float*)d_in[7];   // [16, 1]
    const float* b3  = (const float*)d_in[8];   // [1]
    float* out = (float*)d_out;

    const int M  = in_sizes[0] / 2;   // 2048
    const int BN = in_sizes[1] / 2;   // 8192

    sigma_kernel<<<BN / 8, 256>>>(emb, w1, b1, w2, b2, w3, b3, BN);
    rbf_kernel<<<BN / 16, 256>>>(z, mu, out, M);
}

// round 2
// speedup vs baseline: 1.4200x; 1.4200x over previous
#include <cuda_runtime.h>
#include <cstdint>
#include <cstddef>

// ---------------------------------------------------------------------------
// DataDependentRBFKernel
//   sigma = MLP(embeddings)  (256 -> 32 -> 16 -> 1, exact gelu, sigmoid,
//                             affine to [0.1, 10])
//   out[b,n,m] = exp(-||z[m] - mu[b,n]||^2 / (2 sigma[b,n]^2))
// ---------------------------------------------------------------------------

#define EDIM 256
#define H1DIM 32
#define H2DIM 16
#define SROWS 32          // rows per sigma block

__device__ float g_scale[65536];  // scratch: B*N = 8192 rows (margin)

__device__ __forceinline__ float ex2_approx(float x) {
    float y;
    asm("ex2.approx.f32 %0, %1;" : "=f"(y) : "f"(x));
    return y;
}

__device__ __forceinline__ float gelu_exact(float x) {
    return 0.5f * x * (1.0f + erff(x * 0.70710678118654752440f));
}

// -------------------- sigma MLP: 32 rows per 256-thread block --------------
// Layer 1: warp w computes rows 4w..4w+3 with 4 accumulators; lane = unit j.
// w1 staged in smem [k][j] (conflict-free), reused across the 4 rows.
// e read straight from global as broadcast LDG.128 (L1/L2-resident stream).
__global__ __launch_bounds__(256)
void sigma_kernel(const float* __restrict__ emb,
                  const float* __restrict__ w1, const float* __restrict__ b1,
                  const float* __restrict__ w2, const float* __restrict__ b2,
                  const float* __restrict__ w3, const float* __restrict__ b3)
{
    __shared__ float w1_s[EDIM * H1DIM];      // 32 KB, [k][j]
    __shared__ float h1_s[SROWS * H1DIM];     // 4 KB
    __shared__ float h2_s[SROWS * H2DIM];     // 2 KB

    const int tid = threadIdx.x;
    const int rowbase = blockIdx.x * SROWS;

    // stage w1 (float4, coalesced): 8192 floats = 2048 float4 / 256 thr
    {
        const float4* w14 = reinterpret_cast<const float4*>(w1);
        float4* w1s4 = reinterpret_cast<float4*>(w1_s);
        #pragma unroll
        for (int i = 0; i < (EDIM * H1DIM / 4) / 256; ++i)
            w1s4[tid + i * 256] = w14[tid + i * 256];
    }
    __syncthreads();

    // ---- layer 1 ----
    {
        const int j = tid & 31;
        const int w = tid >> 5;            // warp id, rows 4w..4w+3
        const int r0 = rowbase + w * 4;
        const float* e0 = emb + (size_t)r0 * EDIM;

        float acc0, acc1, acc2, acc3;
        acc0 = acc1 = acc2 = acc3 = __ldg(&b1[j]);

        #pragma unroll 4
        for (int k = 0; k < EDIM; k += 4) {
            const float wv0 = w1_s[(k + 0) * H1DIM + j];
            const float wv1 = w1_s[(k + 1) * H1DIM + j];
            const float wv2 = w1_s[(k + 2) * H1DIM + j];
            const float wv3 = w1_s[(k + 3) * H1DIM + j];
            float4 e;
            e = __ldg(reinterpret_cast<const float4*>(e0 + 0 * EDIM + k));
            acc0 = fmaf(e.x, wv0, acc0); acc0 = fmaf(e.y, wv1, acc0);
            acc0 = fmaf(e.z, wv2, acc0); acc0 = fmaf(e.w, wv3, acc0);
            e = __ldg(reinterpret_cast<const float4*>(e0 + 1 * EDIM + k));
            acc1 = fmaf(e.x, wv0, acc1); acc1 = fmaf(e.y, wv1, acc1);
            acc1 = fmaf(e.z, wv2, acc1); acc1 = fmaf(e.w, wv3, acc1);
            e = __ldg(reinterpret_cast<const float4*>(e0 + 2 * EDIM + k));
            acc2 = fmaf(e.x, wv0, acc2); acc2 = fmaf(e.y, wv1, acc2);
            acc2 = fmaf(e.z, wv2, acc2); acc2 = fmaf(e.w, wv3, acc2);
            e = __ldg(reinterpret_cast<const float4*>(e0 + 3 * EDIM + k));
            acc3 = fmaf(e.x, wv0, acc3); acc3 = fmaf(e.y, wv1, acc3);
            acc3 = fmaf(e.z, wv2, acc3); acc3 = fmaf(e.w, wv3, acc3);
        }
        h1_s[(w * 4 + 0) * H1DIM + j] = gelu_exact(acc0);
        h1_s[(w * 4 + 1) * H1DIM + j] = gelu_exact(acc1);
        h1_s[(w * 4 + 2) * H1DIM + j] = gelu_exact(acc2);
        h1_s[(w * 4 + 3) * H1DIM + j] = gelu_exact(acc3);
    }
    __syncthreads();

    // ---- layer 2: 32 rows x 16 units = 512 items, 2 per thread ----
    {
        #pragma unroll
        for (int it = 0; it < 2; ++it) {
            const int item = tid + it * 256;
            const int r = item >> 4;
            const int m = item & 15;
            float acc = __ldg(&b2[m]);
            #pragma unroll
            for (int j = 0; j < H1DIM; ++j)
                acc = fmaf(h1_s[r * H1DIM + j], __ldg(&w2[j * H2DIM + m]), acc);
            h2_s[r * H2DIM + m] = gelu_exact(acc);
        }
    }
    __syncthreads();

    // ---- layer 3 + sigmoid + affine; fold log2(e) into the scale ----
    if (tid < SROWS) {
        float s = __ldg(&b3[0]);
        #pragma unroll
        for (int m = 0; m < H2DIM; ++m)
            s = fmaf(h2_s[tid * H2DIM + m], __ldg(&w3[m]), s);
        float sig = 1.0f / (1.0f + expf(-s));
        float sigma = 0.1f + 9.9f * sig;
        g_scale[rowbase + tid] = -1.44269504088896340736f / (2.0f * sigma * sigma);
    }
}

// -------------------- RBF sweep: 8 rows x 1024 z per 256-thread block ------
// Thread t owns 4 contiguous z points (registers), writes one STG.128 per row.
// Grid: (M/1024, BN/8) = (2, 1024) -> ~14 CTAs/SM of work.
__global__ __launch_bounds__(256)
void rbf_kernel(const float* __restrict__ z, const float* __restrict__ mu,
                float* __restrict__ out, int M)
{
    constexpr int TILE_R = 8;
    __shared__ float  sc_s[TILE_R];
    __shared__ float2 mu_s[TILE_R];

    const int t = threadIdx.x;
    const int zb = blockIdx.x * 1024 + t * 4;     // first of 4 z points
    const int rowbase = blockIdx.y * TILE_R;

    if (t < TILE_R) {
        sc_s[t] = g_scale[rowbase + t];
        mu_s[t] = reinterpret_cast<const float2*>(mu)[rowbase + t];
    }

    // 4 z points: z is [M,2] interleaved -> 2 float4 loads
    float z0[4], z1[4], r2[4];
    {
        const float4* z4 = reinterpret_cast<const float4*>(z);
        #pragma unroll
        for (int i = 0; i < 2; ++i) {
            float4 v = z4[(size_t)zb / 2 + i];
            z0[2 * i]     = v.x;  z1[2 * i]     = v.y;
            z0[2 * i + 1] = v.z;  z1[2 * i + 1] = v.w;
        }
        #pragma unroll
        for (int i = 0; i < 4; ++i)
            r2[i] = z0[i] * z0[i] + z1[i] * z1[i];
    }
    __syncthreads();

    const size_t base = (size_t)rowbase * (size_t)M + (size_t)zb;

    #pragma unroll
    for (int r = 0; r < TILE_R; ++r) {
        const float  sc = sc_s[r];
        const float2 muv = mu_s[r];
        const float  c0 = -2.0f * sc * muv.x;
        const float  c1 = -2.0f * sc * muv.y;
        const float  cc = sc * (muv.x * muv.x + muv.y * muv.y);

        float o[4];
        #pragma unroll
        for (int i = 0; i < 4; ++i) {
            float a = fmaf(sc, r2[i], fmaf(c0, z0[i], fmaf(c1, z1[i], cc)));
            o[i] = ex2_approx(a);
        }
        *reinterpret_cast<float4*>(out + base + (size_t)r * M) =
            make_float4(o[0], o[1], o[2], o[3]);
    }
}

// ---------------------------------------------------------------------------
extern "C" void kernel_launch(void* const* d_in, const int* in_sizes, int n_in,
                              void* d_out, int out_size)
{
    const float* z   = (const float*)d_in[0];   // [M, 2]
    const float* mu  = (const float*)d_in[1];   // [B, N, 2]
    const float* emb = (const float*)d_in[2];   // [B, N, 256]
    const float* w1  = (const float*)d_in[3];   // [256, 32]
    const float* b1  = (const float*)d_in[4];   // [32]
    const float* w2  = (const float*)d_in[5];   // [32, 16]
    const float* b2  = (const float*)d_in[6];   // [16]
    const float* w3  = (const float*)d_in[7];   // [16, 1]
    const float* b3  = (const float*)d_in[8];   // [1]
    float* out = (float*)d_out;

    const int M  = in_sizes[0] / 2;   // 2048
    const int BN = in_sizes[1] / 2;   // 8192

    sigma_kernel<<<BN / SROWS, 256>>>(emb, w1, b1, w2, b2, w3, b3);

    dim3 grid(M / 1024, BN / 8);
    rbf_kernel<<<grid, 256>>>(z, mu, out, M);
}

// round 4
// speedup vs baseline: 1.6818x; 1.1844x over previous
#include <cuda_runtime.h>
#include <cstdint>
#include <cstddef>

// ---------------------------------------------------------------------------
// DataDependentRBFKernel
//   sigma = MLP(embeddings)  (256 -> 32 -> 16 -> 1, exact gelu, sigmoid,
//                             affine to [0.1, 10])
//   out[b,n,m] = exp(-||z[m] - mu[b,n]||^2 / (2 sigma[b,n]^2))
//
// sigma_kernel: fully smem-staged MLP, 32 rows/block; also folds mu into
//               per-row coefficients (sc, c0, c1, cc) -> g_coef.
// rbf_kernel:   L2-store-bound sweep, 8 rows x 1024 z per block.
// ---------------------------------------------------------------------------

#define EDIM 256
#define H1DIM 32
#define H2DIM 16
#define SROWS 32

__device__ float4 g_coef[8192];   // per-row (sc, c0, c1, cc)

__device__ __forceinline__ float ex2_approx(float x) {
    float y;
    asm("ex2.approx.f32 %0, %1;" : "=f"(y) : "f"(x));
    return y;
}

__device__ __forceinline__ float gelu_exact(float x) {
    return 0.5f * x * (1.0f + erff(x * 0.70710678118654752440f));
}

// -------------------- sigma MLP: 32 rows per 256-thread block --------------
// Dynamic smem layout (floats):
//   e_s  [32*256]  32 KB
//   w1_s [256*32]  32 KB   ([k][j], j contiguous -> conflict-free)
//   w2_s [32*16]    2 KB
//   h1_s [32*32]    4 KB
//   h2_s [32*16]    2 KB
__global__ __launch_bounds__(256)
void sigma_kernel(const float* __restrict__ emb, const float* __restrict__ mu,
                  const float* __restrict__ w1, const float* __restrict__ b1,
                  const float* __restrict__ w2, const float* __restrict__ b2,
                  const float* __restrict__ w3, const float* __restrict__ b3)
{
    extern __shared__ float smem[];
    float* e_s  = smem;                       // 8192
    float* w1_s = e_s + SROWS * EDIM;         // 8192
    float* w2_s = w1_s + EDIM * H1DIM;        // 512
    float* h1_s = w2_s + H1DIM * H2DIM;       // 1024
    float* h2_s = h1_s + SROWS * H1DIM;       // 512

    const int tid = threadIdx.x;
    const int rowbase = blockIdx.x * SROWS;

    // ---- cooperative staging (float4, coalesced, deep MLP) ----
    {
        const float4* e4 = reinterpret_cast<const float4*>(emb + (size_t)rowbase * EDIM);
        float4* es4 = reinterpret_cast<float4*>(e_s);
        #pragma unroll
        for (int i = 0; i < (SROWS * EDIM / 4) / 256; ++i)   // 8
            es4[tid + i * 256] = e4[tid + i * 256];

        const float4* w14 = reinterpret_cast<const float4*>(w1);
        float4* w1s4 = reinterpret_cast<float4*>(w1_s);
        #pragma unroll
        for (int i = 0; i < (EDIM * H1DIM / 4) / 256; ++i)   // 8
            w1s4[tid + i * 256] = w14[tid + i * 256];

        if (tid < (H1DIM * H2DIM / 4)) {                     // 128
            reinterpret_cast<float4*>(w2_s)[tid] =
                reinterpret_cast<const float4*>(w2)[tid];
        }
    }
    __syncthreads();

    // ---- layer 1: warp w -> rows 4w..4w+3, lane = unit j ----
    {
        const int j = tid & 31;
        const int w = tid >> 5;
        const float* e0 = e_s + (w * 4) * EDIM;

        float acc0, acc1, acc2, acc3;
        acc0 = acc1 = acc2 = acc3 = __ldg(&b1[j]);

        #pragma unroll 8
        for (int k = 0; k < EDIM; k += 4) {
            const float wv0 = w1_s[(k + 0) * H1DIM + j];
            const float wv1 = w1_s[(k + 1) * H1DIM + j];
            const float wv2 = w1_s[(k + 2) * H1DIM + j];
            const float wv3 = w1_s[(k + 3) * H1DIM + j];
            float4 e;
            e = *reinterpret_cast<const float4*>(e0 + 0 * EDIM + k);
            acc0 = fmaf(e.x, wv0, acc0); acc0 = fmaf(e.y, wv1, acc0);
            acc0 = fmaf(e.z, wv2, acc0); acc0 = fmaf(e.w, wv3, acc0);
            e = *reinterpret_cast<const float4*>(e0 + 1 * EDIM + k);
            acc1 = fmaf(e.x, wv0, acc1); acc1 = fmaf(e.y, wv1, acc1);
            acc1 = fmaf(e.z, wv2, acc1); acc1 = fmaf(e.w, wv3, acc1);
            e = *reinterpret_cast<const float4*>(e0 + 2 * EDIM + k);
            acc2 = fmaf(e.x, wv0, acc2); acc2 = fmaf(e.y, wv1, acc2);
            acc2 = fmaf(e.z, wv2, acc2); acc2 = fmaf(e.w, wv3, acc2);
            e = *reinterpret_cast<const float4*>(e0 + 3 * EDIM + k);
            acc3 = fmaf(e.x, wv0, acc3); acc3 = fmaf(e.y, wv1, acc3);
            acc3 = fmaf(e.z, wv2, acc3); acc3 = fmaf(e.w, wv3, acc3);
        }
        h1_s[(w * 4 + 0) * H1DIM + j] = gelu_exact(acc0);
        h1_s[(w * 4 + 1) * H1DIM + j] = gelu_exact(acc1);
        h1_s[(w * 4 + 2) * H1DIM + j] = gelu_exact(acc2);
        h1_s[(w * 4 + 3) * H1DIM + j] = gelu_exact(acc3);
    }
    __syncthreads();

    // ---- layer 2: 32 rows x 16 units = 512 items, 2 per thread ----
    {
        #pragma unroll
        for (int it = 0; it < 2; ++it) {
            const int item = tid + it * 256;
            const int r = item >> 4;
            const int m = item & 15;
            float acc = __ldg(&b2[m]);
            #pragma unroll
            for (int j = 0; j < H1DIM; ++j)
                acc = fmaf(h1_s[r * H1DIM + j], w2_s[j * H2DIM + m], acc);
            h2_s[r * H2DIM + m] = gelu_exact(acc);
        }
    }
    __syncthreads();

    // ---- layer 3 + sigmoid + affine + fold mu into coefficients ----
    if (tid < SROWS) {
        float s = __ldg(&b3[0]);
        #pragma unroll
        for (int m = 0; m < H2DIM; ++m)
            s = fmaf(h2_s[tid * H2DIM + m], __ldg(&w3[m]), s);
        const float sig = 1.0f / (1.0f + expf(-s));
        const float sigma = 0.1f + 9.9f * sig;
        // base-2 scale: arg = sc*|z|^2 + c0*z0 + c1*z1 + cc
        const float sc = -1.44269504088896340736f / (2.0f * sigma * sigma);
        const float2 muv = reinterpret_cast<const float2*>(mu)[rowbase + tid];
        const float c0 = -2.0f * sc * muv.x;
        const float c1 = -2.0f * sc * muv.y;
        const float cc = sc * (muv.x * muv.x + muv.y * muv.y);
        g_coef[rowbase + tid] = make_float4(sc, c0, c1, cc);
    }
}

// -------------------- RBF sweep: 8 rows x 1024 z per 256-thread block ------
__global__ __launch_bounds__(256)
void rbf_kernel(const float* __restrict__ z, float* __restrict__ out, int M)
{
    constexpr int TILE_R = 8;
    __shared__ float4 coef_s[TILE_R];

    const int t = threadIdx.x;
    const int zb = blockIdx.x * 1024 + t * 4;
    const int rowbase = blockIdx.y * TILE_R;

    if (t < TILE_R)
        coef_s[t] = g_coef[rowbase + t];

    // 4 z points: z is [M,2] interleaved -> 2 float4 loads
    float z0[4], z1[4], r2[4];
    {
        const float4* z4 = reinterpret_cast<const float4*>(z);
        #pragma unroll
        for (int i = 0; i < 2; ++i) {
            float4 v = z4[(size_t)(blockIdx.x * 512) + (size_t)t * 2 + i];
            z0[2 * i]     = v.x;  z1[2 * i]     = v.y;
            z0[2 * i + 1] = v.z;  z1[2 * i + 1] = v.w;
        }
        #pragma unroll
        for (int i = 0; i < 4; ++i)
            r2[i] = z0[i] * z0[i] + z1[i] * z1[i];
    }
    __syncthreads();

    float* optr = out + (size_t)rowbase * (size_t)M + (size_t)zb;

    #pragma unroll
    for (int r = 0; r < TILE_R; ++r) {
        const float4 c = coef_s[r];
        float o[4];
        #pragma unroll
        for (int i = 0; i < 4; ++i) {
            float a = fmaf(c.x, r2[i], fmaf(c.y, z0[i], fmaf(c.z, z1[i], c.w)));
            o[i] = ex2_approx(a);
        }
        *reinterpret_cast<float4*>(optr) = make_float4(o[0], o[1], o[2], o[3]);
        optr += M;
    }
}

// ---------------------------------------------------------------------------
extern "C" void kernel_launch(void* const* d_in, const int* in_sizes, int n_in,
                              void* d_out, int out_size)
{
    const float* z   = (const float*)d_in[0];   // [M, 2]
    const float* mu  = (const float*)d_in[1];   // [B, N, 2]
    const float* emb = (const float*)d_in[2];   // [B, N, 256]
    const float* w1  = (const float*)d_in[3];   // [256, 32]
    const float* b1  = (const float*)d_in[4];   // [32]
    const float* w2  = (const float*)d_in[5];   // [32, 16]
    const float* b2  = (const float*)d_in[6];   // [16]
    const float* w3  = (const float*)d_in[7];   // [16, 1]
    const float* b3  = (const float*)d_in[8];   // [1]
    float* out = (float*)d_out;

    const int M  = in_sizes[0] / 2;   // 2048
    const int BN = in_sizes[1] / 2;   // 8192

    const int smem_bytes = (SROWS * EDIM + EDIM * H1DIM + H1DIM * H2DIM +
                            SROWS * H1DIM + SROWS * H2DIM) * sizeof(float);
    static bool attr_set = false;
    if (!attr_set) {
        cudaFuncSetAttribute(sigma_kernel,
                             cudaFuncAttributeMaxDynamicSharedMemorySize,
                             smem_bytes);
        attr_set = true;
    }

    sigma_kernel<<<BN / SROWS, 256, smem_bytes>>>(emb, mu, w1, b1, w2, b2, w3, b3);

    dim3 grid(M / 1024, BN / 8);
    rbf_kernel<<<grid, 256>>>(z, out, M);
}